// round 15
// baseline (speedup 1.0000x reference)
#include <cuda_runtime.h>

#define NN 100000
#define NE 600000
#define CIN 16
#define HW 48
#define NL 5
#define EB ((NE + 127) / 128)

typedef unsigned long long u64;

// ---- scratch (device globals: allocation-guard safe) ----
__device__ float  g_x1[NN * CIN];
__device__ float  g_x2[NN * CIN];
__device__ float  g_agg[NN * CIN];
__device__ float  g_cnt[NN];
__device__ float  g_ef1[(size_t)NE * HW];   // 115 MB intermediate edge features
__device__ double g_sl[2];

// ---- EdgeConv biases + layer0 weights in the constant bank ----
// b0[48]@0  bh[240]@48  w0[1536]@288   (total 1824 f = 7.3KB)
#define C_B0 0
#define C_BH 48
#define C_W0 288
__constant__ __align__(16) float c_ec[1824];

// ---- f32x2 helpers ----
__device__ __forceinline__ u64 fma2(u64 a, u64 b, u64 c) {
    u64 d;
    asm("fma.rn.f32x2 %0,%1,%2,%3;" : "=l"(d) : "l"(a), "l"(b), "l"(c));
    return d;
}
__device__ __forceinline__ u64 bcast2(float v) {
    u64 r;
    asm("mov.b64 %0,{%1,%1};" : "=l"(r) : "f"(v));
    return r;
}
union Q4 { float4 f4; u64 u[2]; };
union P2 { u64 u; float2 f; };

// ---------------------------------------------------------------------------
__global__ void zero_kernel(int phase) {
    int i = blockIdx.x * blockDim.x + threadIdx.x;
    if (i < NN * CIN) g_agg[i] = 0.f;
    if (i < NN)       g_cnt[i] = 0.f;
    if (phase == 0 && i < 2) g_sl[i] = 0.0;
}

// ---------------------------------------------------------------------------
// NodeConv message + scatter (f32x2-packed MLP: 16 outputs = 8 pair-accs).
__global__ __launch_bounds__(128) void nc_kernel(
    const float* __restrict__ x, const int* __restrict__ ei,
    const float* __restrict__ ang,
    const float* __restrict__ w0, const float* __restrict__ b0,
    const float* __restrict__ wh, const float* __restrict__ bh)
{
    __shared__ __align__(16) float sw0[33 * 16];
    __shared__ __align__(16) float sb0[16];
    __shared__ __align__(16) float swh[5 * 16 * 16];
    __shared__ __align__(16) float sbh[5 * 16];
    int t = threadIdx.x;
    for (int i = t; i < 33 * 16; i += 128) sw0[i] = w0[i];
    for (int i = t; i < 16;      i += 128) sb0[i] = b0[i];
    for (int i = t; i < 5 * 256; i += 128) swh[i] = wh[i];
    for (int i = t; i < 80;      i += 128) sbh[i] = bh[i];
    __syncthreads();

    int e = blockIdx.x * 128 + t;
    if (e >= NE) return;
    int s = ei[e];
    int d = ei[NE + e];

    float in[33];
    const float4* xd4 = (const float4*)(x + (size_t)d * CIN);
    const float4* xs4 = (const float4*)(x + (size_t)s * CIN);
    #pragma unroll
    for (int q = 0; q < 4; q++) {
        float4 v = xd4[q];
        in[q * 4 + 0] = v.x; in[q * 4 + 1] = v.y; in[q * 4 + 2] = v.z; in[q * 4 + 3] = v.w;
    }
    #pragma unroll
    for (int q = 0; q < 4; q++) {
        float4 v = xs4[q];
        in[16 + q * 4 + 0] = v.x; in[16 + q * 4 + 1] = v.y;
        in[16 + q * 4 + 2] = v.z; in[16 + q * 4 + 3] = v.w;
    }
    in[32] = ang[e];

    u64 acc[8];
    float h[16];
    #pragma unroll
    for (int jp = 0; jp < 8; jp++) acc[jp] = *(const u64*)(sb0 + 2 * jp);
    #pragma unroll
    for (int k = 0; k < 33; k++) {
        u64 vp = bcast2(in[k]);
        const float4* wr = (const float4*)(sw0 + k * 16);
        #pragma unroll
        for (int q = 0; q < 4; q++) {
            Q4 w; w.f4 = wr[q];
            acc[2 * q + 0] = fma2(vp, w.u[0], acc[2 * q + 0]);
            acc[2 * q + 1] = fma2(vp, w.u[1], acc[2 * q + 1]);
        }
    }
    #pragma unroll
    for (int jp = 0; jp < 8; jp++) {
        P2 p; p.u = acc[jp];
        h[2 * jp + 0] = fmaxf(p.f.x, 0.f);
        h[2 * jp + 1] = fmaxf(p.f.y, 0.f);
    }

    #pragma unroll 1
    for (int l = 0; l < NL; l++) {
        const float* wl = swh + l * 256;
        const float* bl = sbh + l * 16;
        #pragma unroll
        for (int jp = 0; jp < 8; jp++) acc[jp] = *(const u64*)(bl + 2 * jp);
        #pragma unroll
        for (int k = 0; k < 16; k++) {
            u64 vp = bcast2(h[k]);
            const float4* wr = (const float4*)(wl + k * 16);
            #pragma unroll
            for (int q = 0; q < 4; q++) {
                Q4 w; w.f4 = wr[q];
                acc[2 * q + 0] = fma2(vp, w.u[0], acc[2 * q + 0]);
                acc[2 * q + 1] = fma2(vp, w.u[1], acc[2 * q + 1]);
            }
        }
        #pragma unroll
        for (int jp = 0; jp < 8; jp++) {
            P2 p; p.u = acc[jp];
            h[2 * jp + 0] = fmaxf(p.f.x, 0.f);
            h[2 * jp + 1] = fmaxf(p.f.y, 0.f);
        }
    }

    #pragma unroll
    for (int j = 0; j < 16; j++) atomicAdd(&g_agg[(size_t)d * CIN + j], h[j]);
    atomicAdd(&g_cnt[d], 1.f);
}

// ---------------------------------------------------------------------------
__global__ void div_kernel(float* __restrict__ out) {
    int i = blockIdx.x * blockDim.x + threadIdx.x;
    if (i >= NN * CIN) return;
    float c = g_cnt[i / CIN];
    out[i] = g_agg[i] / fmaxf(c, 1.f);
}

// ---------------------------------------------------------------------------
// EdgeConv, f32x2-packed, fused dual-pass, j-half-split for 3 blocks/SM:
//  - h0/h1 stay in REGISTERS through every k-loop (R14 lesson)
//  - each layer computes outputs in two halves of 24 (acc = 48 regs, not 96);
//    half-A results are parked in a per-thread smem column at the LAYER
//    BOUNDARY only (48 STS + 48 LDS per layer, private, no syncs)
//  - layer-0 weights + all biases come from the constant bank (disjoint port;
//    layer0 LDC floor == its fma time, ~free), wh from smem
//  - smem/block = wh(45KB) + bounce(24KB) = 69KB -> 72KB page -> 3 blocks/SM
//  - combine weights reuse the bounce region after the fold (R14 trick)
// IS_EC1=1: combine [fe, action](49) -> 48, out = g_ef1
// IS_EC1=0: combine [fe, ef1](96)   -> 1,  out = d_out
template <int IS_EC1>
__global__ __launch_bounds__(128, 3) void ec_kernel(
    const float* __restrict__ x, const int* __restrict__ ei,
    const float* __restrict__ extra,
    const float* __restrict__ wh,
    const float* __restrict__ wc, const float* __restrict__ bc,
    float* __restrict__ out, int sli)
{
    extern __shared__ float smem[];
    float* swh = smem;                 // 11520
    float* bb  = smem + 11520;         // bounce 2*24*128 = 6144 (reused for wc)
    float* b0p = bb;                   // pass0 half-A park [24][128]
    float* b1p = bb + 24 * 128;        // pass1 half-A park

    int t = threadIdx.x;
    for (int i = t; i < 11520; i += 128) swh[i] = wh[i];

    int e = blockIdx.x * 128 + t;
    bool active = (e < NE);
    float xd[16], xs[16];
    if (active) {
        int s = ei[e];
        int d = ei[NE + e];
        const float4* a4 = (const float4*)(x + (size_t)d * CIN);
        const float4* b4 = (const float4*)(x + (size_t)s * CIN);
        #pragma unroll
        for (int q = 0; q < 4; q++) {
            float4 v = a4[q];
            xd[q * 4 + 0] = v.x; xd[q * 4 + 1] = v.y; xd[q * 4 + 2] = v.z; xd[q * 4 + 3] = v.w;
            float4 w = b4[q];
            xs[q * 4 + 0] = w.x; xs[q * 4 + 1] = w.y; xs[q * 4 + 2] = w.z; xs[q * 4 + 3] = w.w;
        }
    }
    __syncthreads();   // wh ready

    float sq = 0.f;
    float h0[48], h1[48];
    if (active) {
        u64 a0[12], a1[12];

        // ================= layer 0: 32 -> 48, w0/b0 from const =================
        #pragma unroll
        for (int half = 0; half < 2; half++) {
            int jb = half * 24;   // output base (compile-time: loop unrolled)
            #pragma unroll
            for (int jp = 0; jp < 12; jp++) {
                u64 b = *(const u64*)(c_ec + C_B0 + jb + 2 * jp);
                a0[jp] = b; a1[jp] = b;
            }
            #pragma unroll
            for (int k = 0; k < 32; k++) {
                float v0 = (k < 16) ? xd[k & 15] : xs[k & 15];
                float v1 = (k < 16) ? xs[k & 15] : xd[k & 15];
                u64 p0 = bcast2(v0);
                u64 p1 = bcast2(v1);
                const float4* wr = (const float4*)(c_ec + C_W0 + k * 48 + jb);
                #pragma unroll
                for (int q = 0; q < 6; q++) {
                    Q4 w; w.f4 = wr[q];
                    a0[2 * q + 0] = fma2(p0, w.u[0], a0[2 * q + 0]);
                    a0[2 * q + 1] = fma2(p0, w.u[1], a0[2 * q + 1]);
                    a1[2 * q + 0] = fma2(p1, w.u[0], a1[2 * q + 0]);
                    a1[2 * q + 1] = fma2(p1, w.u[1], a1[2 * q + 1]);
                }
            }
            if (half == 0) {   // park half A
                #pragma unroll
                for (int jp = 0; jp < 12; jp++) {
                    P2 p; p.u = a0[jp];
                    b0p[(2 * jp + 0) * 128 + t] = fmaxf(p.f.x, 0.f);
                    b0p[(2 * jp + 1) * 128 + t] = fmaxf(p.f.y, 0.f);
                    P2 r; r.u = a1[jp];
                    b1p[(2 * jp + 0) * 128 + t] = fmaxf(r.f.x, 0.f);
                    b1p[(2 * jp + 1) * 128 + t] = fmaxf(r.f.y, 0.f);
                }
            } else {           // half B straight to regs
                #pragma unroll
                for (int jp = 0; jp < 12; jp++) {
                    P2 p; p.u = a0[jp];
                    h0[24 + 2 * jp + 0] = fmaxf(p.f.x, 0.f);
                    h0[24 + 2 * jp + 1] = fmaxf(p.f.y, 0.f);
                    P2 r; r.u = a1[jp];
                    h1[24 + 2 * jp + 0] = fmaxf(r.f.x, 0.f);
                    h1[24 + 2 * jp + 1] = fmaxf(r.f.y, 0.f);
                }
            }
        }
        #pragma unroll
        for (int j = 0; j < 24; j++) {   // unpark half A
            h0[j] = b0p[j * 128 + t];
            h1[j] = b1p[j * 128 + t];
        }

        // ================= hidden layers: 48 -> 48, x5 =================
        #pragma unroll 1
        for (int l = 0; l < NL; l++) {
            const float* wl = swh + l * 2304;
            const float* bl = c_ec + C_BH + l * 48;
            #pragma unroll
            for (int half = 0; half < 2; half++) {
                int jb = half * 24;
                #pragma unroll
                for (int jp = 0; jp < 12; jp++) {
                    u64 b = *(const u64*)(bl + jb + 2 * jp);
                    a0[jp] = b; a1[jp] = b;
                }
                #pragma unroll
                for (int k = 0; k < 48; k++) {
                    u64 p0 = bcast2(h0[k]);
                    u64 p1 = bcast2(h1[k]);
                    const float4* wr = (const float4*)(wl + k * 48 + jb);
                    #pragma unroll
                    for (int q = 0; q < 6; q++) {
                        Q4 w; w.f4 = wr[q];
                        a0[2 * q + 0] = fma2(p0, w.u[0], a0[2 * q + 0]);
                        a0[2 * q + 1] = fma2(p0, w.u[1], a0[2 * q + 1]);
                        a1[2 * q + 0] = fma2(p1, w.u[0], a1[2 * q + 0]);
                        a1[2 * q + 1] = fma2(p1, w.u[1], a1[2 * q + 1]);
                    }
                }
                if (half == 0) {
                    #pragma unroll
                    for (int jp = 0; jp < 12; jp++) {
                        P2 p; p.u = a0[jp];
                        b0p[(2 * jp + 0) * 128 + t] = fmaxf(p.f.x, 0.f);
                        b0p[(2 * jp + 1) * 128 + t] = fmaxf(p.f.y, 0.f);
                        P2 r; r.u = a1[jp];
                        b1p[(2 * jp + 0) * 128 + t] = fmaxf(r.f.x, 0.f);
                        b1p[(2 * jp + 1) * 128 + t] = fmaxf(r.f.y, 0.f);
                    }
                } else {
                    #pragma unroll
                    for (int jp = 0; jp < 12; jp++) {
                        P2 p; p.u = a0[jp];
                        h0[24 + 2 * jp + 0] = fmaxf(p.f.x, 0.f);
                        h0[24 + 2 * jp + 1] = fmaxf(p.f.y, 0.f);
                        P2 r; r.u = a1[jp];
                        h1[24 + 2 * jp + 0] = fmaxf(r.f.x, 0.f);
                        h1[24 + 2 * jp + 1] = fmaxf(r.f.y, 0.f);
                    }
                }
            }
            #pragma unroll
            for (int j = 0; j < 24; j++) {
                h0[j] = b0p[j * 128 + t];
                h1[j] = b1p[j * 128 + t];
            }
        }

        // ---- side loss + fe (fe overwrites h0) ----
        #pragma unroll
        for (int j = 0; j < 48; j++) {
            float dl = h0[j] - h1[j];
            sq += dl * dl;
            h0[j] = 0.5f * (h0[j] + h1[j]);
        }
    }

    // ---- combine weights into the (now free) bounce region ----
    const int WCN = IS_EC1 ? 49 * 48 : 96;
    const int BCN = IS_EC1 ? 48 : 1;
    __syncthreads();   // everyone finished with bounce
    for (int i = t; i < WCN; i += 128) bb[i] = wc[i];
    for (int i = t; i < BCN; i += 128) bb[WCN + i] = bc[i];
    __syncthreads();

    if (active) {
        const float* swc = bb;
        const float* sbc = bb + WCN;
        if (IS_EC1) {
            float aact = extra[e];
            u64 o[24];
            #pragma unroll
            for (int jp = 0; jp < 24; jp++) o[jp] = *(const u64*)(sbc + 2 * jp);
            {   // action row (row 48)
                u64 ap = bcast2(aact);
                const float4* wr = (const float4*)(swc + 48 * 48);
                #pragma unroll
                for (int q = 0; q < 12; q++) {
                    Q4 w; w.f4 = wr[q];
                    o[2 * q + 0] = fma2(ap, w.u[0], o[2 * q + 0]);
                    o[2 * q + 1] = fma2(ap, w.u[1], o[2 * q + 1]);
                }
            }
            #pragma unroll
            for (int k = 0; k < 48; k++) {
                u64 vp = bcast2(h0[k]);
                const float4* wr = (const float4*)(swc + k * 48);
                #pragma unroll
                for (int q = 0; q < 12; q++) {
                    Q4 w; w.f4 = wr[q];
                    o[2 * q + 0] = fma2(vp, w.u[0], o[2 * q + 0]);
                    o[2 * q + 1] = fma2(vp, w.u[1], o[2 * q + 1]);
                }
            }
            #pragma unroll
            for (int q = 0; q < 12; q++) {
                P2 p0; p0.u = o[2 * q + 0];
                P2 p1; p1.u = o[2 * q + 1];
                *(float4*)(out + (size_t)e * 48 + q * 4) =
                    make_float4(p0.f.x, p0.f.y, p1.f.x, p1.f.y);
            }
        } else {
            float o = sbc[0];
            #pragma unroll
            for (int k = 0; k < 48; k++) o += h0[k] * swc[k];
            const float4* ef = (const float4*)(extra + (size_t)e * 48);
            #pragma unroll
            for (int q = 0; q < 12; q++) {
                float4 v = ef[q];
                o += v.x * swc[48 + q * 4 + 0];
                o += v.y * swc[48 + q * 4 + 1];
                o += v.z * swc[48 + q * 4 + 2];
                o += v.w * swc[48 + q * 4 + 3];
            }
            out[e] = o;
        }
    }

    // side-loss reduction: warp shfl -> double atomic
    #pragma unroll
    for (int off = 16; off; off >>= 1)
        sq += __shfl_xor_sync(0xffffffffu, sq, off);
    if ((t & 31) == 0)
        atomicAdd(&g_sl[sli], (double)sq);
}

// ---------------------------------------------------------------------------
__global__ void fin_kernel(float* __restrict__ out) {
    double inv = 1.0 / ((double)NE * 48.0);
    out[NE] = (float)(0.5 * (g_sl[0] * inv + g_sl[1] * inv));
}

// ---------------------------------------------------------------------------
static void fill_const(const float* b0, const float* bh, const float* w0)
{
    cudaMemcpyToSymbolAsync(c_ec, b0, 48 * 4,   (size_t)C_B0 * 4, cudaMemcpyDeviceToDevice);
    cudaMemcpyToSymbolAsync(c_ec, bh, 240 * 4,  (size_t)C_BH * 4, cudaMemcpyDeviceToDevice);
    cudaMemcpyToSymbolAsync(c_ec, w0, 1536 * 4, (size_t)C_W0 * 4, cudaMemcpyDeviceToDevice);
}

extern "C" void kernel_launch(void* const* d_in, const int* in_sizes, int n_in,
                              void* d_out, int out_size)
{
    const float* nf   = (const float*)d_in[0];
    const int*   ei   = (const int*)d_in[1];
    const float* ang  = (const float*)d_in[2];
    const float* act  = (const float*)d_in[4];
    const float* n1w0 = (const float*)d_in[5],  *n1b0 = (const float*)d_in[6];
    const float* n1wh = (const float*)d_in[7],  *n1bh = (const float*)d_in[8];
    const float* n2w0 = (const float*)d_in[9],  *n2b0 = (const float*)d_in[10];
    const float* n2wh = (const float*)d_in[11], *n2bh = (const float*)d_in[12];
    const float* e1w0 = (const float*)d_in[13], *e1b0 = (const float*)d_in[14];
    const float* e1wh = (const float*)d_in[15], *e1bh = (const float*)d_in[16];
    const float* e1wc = (const float*)d_in[17], *e1bc = (const float*)d_in[18];
    const float* e2w0 = (const float*)d_in[19], *e2b0 = (const float*)d_in[20];
    const float* e2wh = (const float*)d_in[21], *e2bh = (const float*)d_in[22];
    const float* e2wc = (const float*)d_in[23], *e2bc = (const float*)d_in[24];
    float* out = (float*)d_out;

    void *px1, *px2, *pef1;
    cudaGetSymbolAddress(&px1, g_x1);
    cudaGetSymbolAddress(&px2, g_x2);
    cudaGetSymbolAddress(&pef1, g_ef1);

    // smem/block: wh(11520) + bounce(2*24*128=6144) = 17664 f = 69KB
    size_t sh = (size_t)(11520 + 2 * 24 * 128) * sizeof(float);
    cudaFuncSetAttribute(ec_kernel<1>, cudaFuncAttributeMaxDynamicSharedMemorySize, (int)sh);
    cudaFuncSetAttribute(ec_kernel<0>, cudaFuncAttributeMaxDynamicSharedMemorySize, (int)sh);
    cudaFuncSetAttribute(ec_kernel<1>, cudaFuncAttributePreferredSharedMemoryCarveout, 100);
    cudaFuncSetAttribute(ec_kernel<0>, cudaFuncAttributePreferredSharedMemoryCarveout, 100);

    // NodeConv1 -> x1
    zero_kernel<<<6250, 256>>>(0);
    nc_kernel<<<EB, 128>>>(nf, ei, ang, n1w0, n1b0, n1wh, n1bh);
    div_kernel<<<6250, 256>>>((float*)px1);
    // EdgeConv1 -> ef1 (E x 48), sl[0]
    fill_const(e1b0, e1bh, e1w0);
    ec_kernel<1><<<EB, 128, sh>>>((const float*)px1, ei, act,
                                  e1wh, e1wc, e1bc, (float*)pef1, 0);
    // NodeConv2 -> x2
    zero_kernel<<<6250, 256>>>(1);
    nc_kernel<<<EB, 128>>>((const float*)px1, ei, ang, n2w0, n2b0, n2wh, n2bh);
    div_kernel<<<6250, 256>>>((float*)px2);
    // EdgeConv2 -> out (E x 1), sl[1]
    fill_const(e2b0, e2bh, e2w0);
    ec_kernel<0><<<EB, 128, sh>>>((const float*)px2, ei, (const float*)pef1,
                                  e2wh, e2wc, e2bc, out, 1);
    if (out_size > NE) fin_kernel<<<1, 1>>>(out);
}